// round 4
// baseline (speedup 1.0000x reference)
#include <cuda_runtime.h>
#include <cstdint>

#define NB 4

// ---------------- static device scratch ----------------
__device__ float g_nx1[NB*2048*3];
__device__ float g_nx2[NB*1024*3];
__device__ float g_nx3[NB*512*3];
__device__ float g_f1[NB*2048*128];
__device__ float g_f2[NB*1024*256];
__device__ float g_f3[NB*512*512];
__device__ int   g_fidx[NB*2048];
__device__ int   g_nidx[NB*2048*64];
__device__ float g_X0[17170432];
__device__ float g_YA[33554432];
__device__ float g_YB[16777216];
// FPS1 bucketed scratch
__device__ float g_gbx[NB*16384];
__device__ float g_gby[NB*16384];
__device__ float g_gbz[NB*16384];
__device__ int   g_gbo[NB*16384];
__device__ int   g_hist[NB*4096];

// ================== FPS stage 1: bucketed exact-skip, one CTA per batch ==================
#define NBUCK 512
__global__ __launch_bounds__(1024)
void fps1_bucket(const float* __restrict__ xyz, int* __restrict__ fidx)
{
    extern __shared__ float sD[];              // dist[16384], 64KB dynamic
    __shared__ float s_ox[NBUCK], s_oy[NBUCK], s_oz[NBUCK];
    __shared__ float s_br[NBUCK], s_th[NBUCK];
    __shared__ float s_ub[NBUCK];
    __shared__ int   s_uo[NBUCK];
    __shared__ float s_ax[NBUCK], s_ay[NBUCK], s_az[NBUCK];
    __shared__ int   s_q[NBUCK];
    __shared__ int   s_qcnt;
    __shared__ float s_cx, s_cy, s_cz;
    __shared__ float s_redv[16]; __shared__ int s_redo[16], s_redb[16];
    __shared__ float s_w6[6][32];
    __shared__ float s_bb[6];
    __shared__ int   s_wscan[32];

    const int b = blockIdx.x, t = threadIdx.x;
    const int lane = t & 31, w = t >> 5;
    const float* base = xyz + (size_t)b*16384*3;
    float* gx = g_gbx + b*16384;
    float* gy = g_gby + b*16384;
    float* gz = g_gbz + b*16384;
    int*   go = g_gbo + b*16384;
    int*   hist = g_hist + b*4096;

    // ---- bbox ----
    float mnx=3e38f,mny=3e38f,mnz=3e38f,mxx=-3e38f,mxy=-3e38f,mxz=-3e38f;
    for (int i = t; i < 16384; i += 1024) {
        float x=base[i*3], y=base[i*3+1], z=base[i*3+2];
        mnx=fminf(mnx,x); mny=fminf(mny,y); mnz=fminf(mnz,z);
        mxx=fmaxf(mxx,x); mxy=fmaxf(mxy,y); mxz=fmaxf(mxz,z);
    }
#pragma unroll
    for (int o=16;o;o>>=1){
        mnx=fminf(mnx,__shfl_xor_sync(~0u,mnx,o));
        mny=fminf(mny,__shfl_xor_sync(~0u,mny,o));
        mnz=fminf(mnz,__shfl_xor_sync(~0u,mnz,o));
        mxx=fmaxf(mxx,__shfl_xor_sync(~0u,mxx,o));
        mxy=fmaxf(mxy,__shfl_xor_sync(~0u,mxy,o));
        mxz=fmaxf(mxz,__shfl_xor_sync(~0u,mxz,o));
    }
    if (lane==0){ s_w6[0][w]=mnx; s_w6[1][w]=mny; s_w6[2][w]=mnz;
                  s_w6[3][w]=mxx; s_w6[4][w]=mxy; s_w6[5][w]=mxz; }
    // zero hist meanwhile
    for (int i=t;i<4096;i+=1024) hist[i]=0;
    __syncthreads();
    if (t==0){
        float a[6];
        for (int q2=0;q2<6;q2++) a[q2]=s_w6[q2][0];
        for (int k=1;k<32;k++){
            a[0]=fminf(a[0],s_w6[0][k]); a[1]=fminf(a[1],s_w6[1][k]); a[2]=fminf(a[2],s_w6[2][k]);
            a[3]=fmaxf(a[3],s_w6[3][k]); a[4]=fmaxf(a[4],s_w6[4][k]); a[5]=fmaxf(a[5],s_w6[5][k]);
        }
        for (int q2=0;q2<6;q2++) s_bb[q2]=a[q2];
        s_qcnt = 0;
    }
    __syncthreads();
    const float bx0=s_bb[0], by0=s_bb[1], bz0=s_bb[2];
    const float scx=16.0f/fmaxf(s_bb[3]-bx0,1e-9f);
    const float scy=16.0f/fmaxf(s_bb[4]-by0,1e-9f);
    const float scz=16.0f/fmaxf(s_bb[5]-bz0,1e-9f);

    // ---- histogram ----
    for (int i=t;i<16384;i+=1024){
        float x=base[i*3], y=base[i*3+1], z=base[i*3+2];
        int cx=min(15,max(0,(int)((x-bx0)*scx)));
        int cy=min(15,max(0,(int)((y-by0)*scy)));
        int cz=min(15,max(0,(int)((z-bz0)*scz)));
        atomicAdd(&hist[(cx<<8)|(cy<<4)|cz],1);
    }
    __syncthreads();
    // ---- exclusive scan of 4096 counts (4 per thread) ----
    {
        int v0=hist[t*4+0], v1=hist[t*4+1], v2=hist[t*4+2], v3=hist[t*4+3];
        int lsum=v0+v1+v2+v3;
        int sc=lsum;
#pragma unroll
        for (int o=1;o<32;o<<=1){ int n=__shfl_up_sync(~0u,sc,o); if (lane>=o) sc+=n; }
        if (lane==31) s_wscan[w]=sc;
        __syncthreads();
        if (t<32){
            int wv=s_wscan[t], ws=wv;
#pragma unroll
            for (int o=1;o<32;o<<=1){ int n=__shfl_up_sync(~0u,ws,o); if (t>=o) ws+=n; }
            s_wscan[t]=ws-wv;
        }
        __syncthreads();
        int excl = sc - lsum + s_wscan[w];
        hist[t*4+0]=excl; hist[t*4+1]=excl+v0; hist[t*4+2]=excl+v0+v1; hist[t*4+3]=excl+v0+v1+v2;
    }
    __syncthreads();
    // ---- scatter (bucketed order) + dist init ----
    for (int i=t;i<16384;i+=1024){
        float x=base[i*3], y=base[i*3+1], z=base[i*3+2];
        int cx=min(15,max(0,(int)((x-bx0)*scx)));
        int cy=min(15,max(0,(int)((y-by0)*scy)));
        int cz=min(15,max(0,(int)((z-bz0)*scz)));
        int pos=atomicAdd(&hist[(cx<<8)|(cy<<4)|cz],1);
        gx[pos]=x; gy[pos]=y; gz[pos]=z; go[pos]=i;
    }
    for (int i=t;i<16384;i+=1024) sD[i]=1e10f;
    __syncthreads();
    // ---- bucket bounding spheres ----
    for (int bk=w; bk<NBUCK; bk+=32){
        int p=bk*32+lane;
        float x=gx[p], y=gy[p], z=gz[p];
        float lx=x,hx=x,ly=y,hy=y,lz=z,hz=z;
#pragma unroll
        for (int o=16;o;o>>=1){
            lx=fminf(lx,__shfl_xor_sync(~0u,lx,o)); hx=fmaxf(hx,__shfl_xor_sync(~0u,hx,o));
            ly=fminf(ly,__shfl_xor_sync(~0u,ly,o)); hy=fmaxf(hy,__shfl_xor_sync(~0u,hy,o));
            lz=fminf(lz,__shfl_xor_sync(~0u,lz,o)); hz=fmaxf(hz,__shfl_xor_sync(~0u,hz,o));
        }
        float ox=0.5f*(lx+hx), oy=0.5f*(ly+hy), oz=0.5f*(lz+hz);
        float dx=x-ox, dy=y-oy, dz=z-oz;
        float r2=dx*dx+dy*dy+dz*dz;
#pragma unroll
        for (int o=16;o;o>>=1) r2=fmaxf(r2,__shfl_xor_sync(~0u,r2,o));
        if (lane==0){
            s_ox[bk]=ox; s_oy[bk]=oy; s_oz[bk]=oz;
            s_br[bk]=sqrtf(r2)*1.0001f + 1e-7f;
            s_th[bk]=3.0e37f;        // force dirty on iter 1
            s_ub[bk]=0.0f; s_uo[bk]=0x7fffffff;
            s_ax[bk]=ox; s_ay[bk]=oy; s_az[bk]=oz;
        }
    }
    if (t==0){ s_cx=base[0]; s_cy=base[1]; s_cz=base[2]; fidx[(size_t)b*2048]=0; }
    __syncthreads();

    // ---- main loop ----
    for (int j=1; j<2048; j++){
        const float cx=s_cx, cy=s_cy, cz=s_cz;
        // phase A: dirty check (one thread per bucket) + warp-aggregated enqueue
        bool dirty=false;
        if (t<NBUCK){
            float dx=s_ox[t]-cx, dy=s_oy[t]-cy, dz=s_oz[t]-cz;
            dirty = (dx*dx+dy*dy+dz*dz) < s_th[t];
        }
        unsigned msk=__ballot_sync(~0u,dirty);
        if (msk){
            int ldr=__ffs(msk)-1, cnt=__popc(msk), bpos=0;
            if (lane==ldr) bpos=atomicAdd(&s_qcnt,cnt);
            bpos=__shfl_sync(~0u,bpos,ldr);
            if (dirty) s_q[bpos+__popc(msk&((1u<<lane)-1u))]=t;
        }
        __syncthreads();
        const int qn=s_qcnt;
        // phase B: process dirty buckets (warp per bucket, 1-deep prefetch)
        {
            int qi = w;
            int bkc = (qi<qn)? s_q[qi] : -1;
            float x=0,y=0,z=0; int orig=0;
            if (bkc>=0){ int p=bkc*32+lane; x=gx[p]; y=gy[p]; z=gz[p]; orig=go[p]; }
            for (; qi<qn; qi+=32){
                int bkn = (qi+32<qn)? s_q[qi+32] : -1;
                float xn=0,yn=0,zn=0; int orign=0;
                if (bkn>=0){ int pn=bkn*32+lane; xn=gx[pn]; yn=gy[pn]; zn=gz[pn]; orign=go[pn]; }
                int p=bkc*32+lane;
                float od=sD[p];
                float dx=x-cx, dy=y-cy, dz=z-cz;
                float nd=fminf(od, dx*dx+dy*dy+dz*dz);
                sD[p]=nd;
                float bv=nd; int bo=orig; float ax=x, ay=y, az=z;
#pragma unroll
                for (int o=16;o;o>>=1){
                    float ov=__shfl_xor_sync(~0u,bv,o);
                    int   oo=__shfl_xor_sync(~0u,bo,o);
                    float oxx=__shfl_xor_sync(~0u,ax,o);
                    float oyy=__shfl_xor_sync(~0u,ay,o);
                    float ozz=__shfl_xor_sync(~0u,az,o);
                    if (ov>bv || (ov==bv && oo<bo)){ bv=ov;bo=oo;ax=oxx;ay=oyy;az=ozz; }
                }
                if (lane==0){
                    s_ub[bkc]=bv; s_uo[bkc]=bo;
                    s_ax[bkc]=ax; s_ay[bkc]=ay; s_az[bkc]=az;
                    float ss=s_br[bkc]+sqrtf(bv)*1.0001f;
                    s_th[bkc]=ss*ss*1.0001f;
                }
                bkc=bkn; x=xn; y=yn; z=zn; orig=orign;
            }
        }
        __syncthreads();
        // phase C: global argmax over bucket maxima
        if (t<NBUCK){
            float v=s_ub[t]; int o_=s_uo[t]; int kb=t;
#pragma unroll
            for (int o=16;o;o>>=1){
                float ov=__shfl_xor_sync(~0u,v,o);
                int oo=__shfl_xor_sync(~0u,o_,o);
                int ob=__shfl_xor_sync(~0u,kb,o);
                if (ov>v || (ov==v && oo<o_)){ v=ov;o_=oo;kb=ob; }
            }
            if (lane==0){ s_redv[w]=v; s_redo[w]=o_; s_redb[w]=kb; }
        }
        __syncthreads();
        if (t<32){
            float v = (t<16)? s_redv[t] : -1.0f;
            int o_  = (t<16)? s_redo[t] : 0x7fffffff;
            int kb  = (t<16)? s_redb[t] : 0;
#pragma unroll
            for (int o=16;o;o>>=1){
                float ov=__shfl_xor_sync(~0u,v,o);
                int oo=__shfl_xor_sync(~0u,o_,o);
                int ob=__shfl_xor_sync(~0u,kb,o);
                if (ov>v || (ov==v && oo<o_)){ v=ov;o_=oo;kb=ob; }
            }
            if (t==0){
                fidx[(size_t)b*2048+j]=o_;
                s_cx=s_ax[kb]; s_cy=s_ay[kb]; s_cz=s_az[kb];
                s_qcnt=0;
            }
        }
        __syncthreads();
    }
}

// ============ FPS stages 2-4: coords fully in registers ============
template<int BLK, int P>
__global__ __launch_bounds__(BLK)
void fps_reg_kernel(const float* __restrict__ xyz, int npoint, int* __restrict__ fidx)
{
    const int N = BLK * P;
    extern __shared__ float sm[];
    float* sx = sm; float* sy = sm + N; float* sz = sm + 2*N;
    __shared__ float rv[32];
    __shared__ int   ri[32];
    __shared__ float s_cx, s_cy, s_cz;

    const int b = blockIdx.x, t = threadIdx.x;
    const float* base = xyz + (size_t)b * N * 3;
    float px[P], py[P], pz[P], dst[P];
#pragma unroll
    for (int k = 0; k < P; k++) {
        int i = t + k*BLK;
        px[k] = base[i*3+0]; py[k] = base[i*3+1]; pz[k] = base[i*3+2];
        sx[i] = px[k]; sy[i] = py[k]; sz[i] = pz[k];
        dst[k] = 1e10f;
    }
    if (t == 0) {
        s_cx = px[0]; s_cy = py[0]; s_cz = pz[0];
        fidx[(size_t)b*npoint] = 0;
    }
    __syncthreads();

    for (int j = 1; j < npoint; j++) {
        const float cx = s_cx, cy = s_cy, cz = s_cz;
        float best = -1.0f; int bi = 0x7fffffff;
#pragma unroll
        for (int k = 0; k < P; k++) {
            float dx = px[k]-cx, dy = py[k]-cy, dz = pz[k]-cz;
            float nd = fminf(dst[k], dx*dx + dy*dy + dz*dz);
            dst[k] = nd;
            if (nd > best) { best = nd; bi = t + k*BLK; }
        }
#pragma unroll
        for (int off = 16; off; off >>= 1) {
            float ov = __shfl_down_sync(0xffffffffu, best, off);
            int   oi = __shfl_down_sync(0xffffffffu, bi,   off);
            if (ov > best || (ov == best && oi < bi)) { best = ov; bi = oi; }
        }
        int w = t >> 5;
        if ((t & 31) == 0) { rv[w] = best; ri[w] = bi; }
        __syncthreads();
        if (t < 32) {
            const int nw = BLK / 32;
            float v  = (t < nw) ? rv[t] : -1.0f;
            int   i2 = (t < nw) ? ri[t] : 0x7fffffff;
#pragma unroll
            for (int off = 16; off; off >>= 1) {
                float ov = __shfl_down_sync(0xffffffffu, v,  off);
                int   oi = __shfl_down_sync(0xffffffffu, i2, off);
                if (ov > v || (ov == v && oi < i2)) { v = ov; i2 = oi; }
            }
            if (t == 0) {
                fidx[(size_t)b*npoint + j] = i2;
                s_cx = sx[i2]; s_cy = sy[i2]; s_cz = sz[i2];
            }
        }
        __syncthreads();
    }
}

__global__ void gather_xyz(const float* __restrict__ xyz, const int* __restrict__ fidx,
                           float* __restrict__ nxyz, int S, int N, int total)
{
    int idx = blockIdx.x*blockDim.x + threadIdx.x;
    if (idx >= total) return;
    int b = idx / (S*3);
    int r = idx % (S*3);
    int s = r / 3, c = r % 3;
    nxyz[idx] = xyz[((size_t)b*N + fidx[b*S + s])*3 + c];
}

__global__ void ball_query_kernel(const float* __restrict__ xyz, const float* __restrict__ nxyz,
                                  int* __restrict__ nidx, int S, int N, int nsample,
                                  float r2, int nwarps)
{
    int gw   = (blockIdx.x*blockDim.x + threadIdx.x) >> 5;
    int lane = threadIdx.x & 31;
    if (gw >= nwarps) return;
    int b = gw / S;
    const float* xb = xyz + (size_t)b * N * 3;
    float nx = nxyz[gw*3+0], ny = nxyz[gw*3+1], nz = nxyz[gw*3+2];
    float sn = (nx*nx + ny*ny) + nz*nz;
    int* out = nidx + (size_t)gw * nsample;

    int cnt = 0, first = -1;
    for (int base = 0; base < N; base += 32) {
        int j = base + lane;
        bool in = false;
        if (j < N) {
            float x = xb[j*3+0], y = xb[j*3+1], z = xb[j*3+2];
            float sxx = (x*x + y*y) + z*z;
            float dot = (nx*x + ny*y) + nz*z;
            in = ((sn + sxx) - 2.0f*dot) < r2;
        }
        unsigned m = __ballot_sync(0xffffffffu, in);
        if (in) {
            int pos = cnt + __popc(m & ((1u << lane) - 1u));
            if (pos < nsample) out[pos] = j;
        }
        if (first < 0 && m) first = base + __ffs(m) - 1;
        cnt += __popc(m);
        if (cnt >= nsample) break;
    }
    for (int p = cnt + lane; p < nsample; p += 32) out[p] = first;
}

// ============ stage 1 fused: group + MLP(3->64->64->128) + maxpool ============
// W2 read from global (L2-hot) to fit 4 blocks/SM.
#define SA1_SMEM 12928
__global__ __launch_bounds__(128)
void sa1_kernel(const float* __restrict__ xyz, const float* __restrict__ nxyz,
                const int* __restrict__ nidx,
                const float* __restrict__ w0, const float* __restrict__ b0,
                const float* __restrict__ w1, const float* __restrict__ b1,
                const float* __restrict__ w2, const float* __restrict__ b2,
                float* __restrict__ feats, float radius)
{
    extern __shared__ float sm[];
    float* sW0 = sm;              // 192
    float* sB0 = sm + 192;        // 64
    float* sW1 = sm + 256;        // 4096
    float* sB1 = sm + 4352;       // 64
    float* sB2 = sm + 4416;       // 128
    float* sR  = sm + 4544;       // 192
    float* sH0 = sm + 4736;       // 64x64 transposed [c][n]
    float* sH1 = sm + 8832;       // 64x64 transposed [c][n]

    const int t = threadIdx.x;
    const int ctr = blockIdx.x;
    const int b = ctr >> 11;

    for (int i = t; i < 192;  i += 128) sW0[i] = w0[i];
    if (t < 64) { sB0[t] = b0[t]; sB1[t] = b1[t]; }
    for (int i = t; i < 4096; i += 128) sW1[i] = w1[i];
    sB2[t] = b2[t];
    if (t < 64) {
        int id = nidx[(size_t)ctr*64 + t];
        const float* p = xyz + ((size_t)(b << 14) + id)*3;
        sR[t*3+0] = (p[0] - nxyz[ctr*3+0]) / radius;
        sR[t*3+1] = (p[1] - nxyz[ctr*3+1]) / radius;
        sR[t*3+2] = (p[2] - nxyz[ctr*3+2]) / radius;
    }
    __syncthreads();

    {
        int n = t & 63, half = t >> 6;
        float rx = sR[n*3+0], ry = sR[n*3+1], rz = sR[n*3+2];
#pragma unroll 8
        for (int cc = 0; cc < 32; cc++) {
            int c = half*32 + cc;
            float v = sB0[c] + rx*sW0[c] + ry*sW0[64+c] + rz*sW0[128+c];
            sH0[c*64 + n] = fmaxf(v, 0.0f);
        }
    }
    __syncthreads();

    const int ng = t & 15, cg = t >> 4;
    float acc[32];

#pragma unroll
    for (int i = 0; i < 4; i++)
#pragma unroll
        for (int jj = 0; jj < 8; jj++) acc[i*8+jj] = sB1[8*cg + jj];
#pragma unroll 8
    for (int k = 0; k < 64; k++) {
        float4 a = *(const float4*)&sH0[k*64 + 4*ng];
        float4 u = *(const float4*)&sW1[k*64 + 8*cg];
        float4 v = *(const float4*)&sW1[k*64 + 8*cg + 4];
        float av[4] = {a.x, a.y, a.z, a.w};
        float bv[8] = {u.x, u.y, u.z, u.w, v.x, v.y, v.z, v.w};
#pragma unroll
        for (int i = 0; i < 4; i++)
#pragma unroll
            for (int jj = 0; jj < 8; jj++) acc[i*8+jj] += av[i]*bv[jj];
    }
#pragma unroll
    for (int jj = 0; jj < 8; jj++) {
        float4 o;
        o.x = fmaxf(acc[0*8+jj], 0.0f);
        o.y = fmaxf(acc[1*8+jj], 0.0f);
        o.z = fmaxf(acc[2*8+jj], 0.0f);
        o.w = fmaxf(acc[3*8+jj], 0.0f);
        *(float4*)&sH1[(8*cg+jj)*64 + 4*ng] = o;
    }
    __syncthreads();

#pragma unroll 1
    for (int pass = 0; pass < 2; pass++) {
        int c0 = pass*64 + 8*cg;
#pragma unroll
        for (int i = 0; i < 4; i++)
#pragma unroll
            for (int jj = 0; jj < 8; jj++) acc[i*8+jj] = sB2[c0 + jj];
#pragma unroll 4
        for (int k = 0; k < 64; k++) {
            float4 a = *(const float4*)&sH1[k*64 + 4*ng];
            float4 u = *(const float4*)&w2[k*128 + c0];
            float4 v = *(const float4*)&w2[k*128 + c0 + 4];
            float av[4] = {a.x, a.y, a.z, a.w};
            float bv[8] = {u.x, u.y, u.z, u.w, v.x, v.y, v.z, v.w};
#pragma unroll
            for (int i = 0; i < 4; i++)
#pragma unroll
                for (int jj = 0; jj < 8; jj++) acc[i*8+jj] += av[i]*bv[jj];
        }
#pragma unroll
        for (int jj = 0; jj < 8; jj++) {
            float m = fmaxf(fmaxf(fmaxf(acc[0*8+jj], 0.0f), fmaxf(acc[1*8+jj], 0.0f)),
                            fmaxf(fmaxf(acc[2*8+jj], 0.0f), fmaxf(acc[3*8+jj], 0.0f)));
#pragma unroll
            for (int off = 8; off; off >>= 1)
                m = fmaxf(m, __shfl_xor_sync(0xffffffffu, m, off));
            if (ng == 0) feats[(size_t)ctr*128 + c0 + jj] = m;
        }
    }
}

__global__ void group_kernel(const float* __restrict__ xyz, const float* __restrict__ nxyz,
                             const int* __restrict__ nidx, const float* __restrict__ feats,
                             float* __restrict__ X0, int S, int N, int ns, int C,
                             float radius, int total)
{
    int idx = blockIdx.x*blockDim.x + threadIdx.x;
    if (idx >= total) return;
    int Cin = 3 + C;
    int row = idx / Cin, c = idx % Cin;
    int b = row / (S*ns);
    int r = row % (S*ns);
    int s = r / ns;
    int id = nidx[row];
    if (c < 3) {
        X0[idx] = (xyz[((size_t)b*N + id)*3 + c] - nxyz[((size_t)b*S + s)*3 + c]) / radius;
    } else {
        X0[idx] = feats[((size_t)b*N + id)*C + (c - 3)];
    }
}

// ============ fp32 GEMM + bias + relu: 128x128 tile, 8x8 micro ============
__global__ __launch_bounds__(256)
void gemm128(const float* __restrict__ A, const float* __restrict__ W,
             const float* __restrict__ bias, float* __restrict__ Y,
             int M, int N, int K)
{
    __shared__ __align__(16) float As[8][128];
    __shared__ __align__(16) float Bs[8][128];
    const int bm = blockIdx.y * 128;
    const int bn = blockIdx.x * 128;
    const int t  = threadIdx.x;
    const int ty = t >> 4, tx = t & 15;
    float acc[8][8];
#pragma unroll
    for (int i = 0; i < 8; i++)
#pragma unroll
        for (int j = 0; j < 8; j++) acc[i][j] = 0.0f;

    const int abr = t >> 5;
    const int abc = (t & 31) * 4;

    for (int k0 = 0; k0 < K; k0 += 8) {
#pragma unroll
        for (int q = 0; q < 4; q++) {
            int e = t*4 + q;
            int ar = e >> 3, ac = e & 7;
            int kk = k0 + ac;
            As[ac][ar] = (kk < K) ? A[(size_t)(bm + ar)*K + kk] : 0.0f;
        }
        {
            int kk = k0 + abr;
            float4 wv = make_float4(0.f, 0.f, 0.f, 0.f);
            if (kk < K) wv = *(const float4*)&W[(size_t)kk*N + bn + abc];
            *(float4*)&Bs[abr][abc] = wv;
        }
        __syncthreads();
#pragma unroll
        for (int kk = 0; kk < 8; kk++) {
            float4 a0 = *(const float4*)&As[kk][ty*8];
            float4 a1 = *(const float4*)&As[kk][ty*8 + 4];
            float4 b0 = *(const float4*)&Bs[kk][tx*8];
            float4 b1 = *(const float4*)&Bs[kk][tx*8 + 4];
            float av[8] = {a0.x, a0.y, a0.z, a0.w, a1.x, a1.y, a1.z, a1.w};
            float bv[8] = {b0.x, b0.y, b0.z, b0.w, b1.x, b1.y, b1.z, b1.w};
#pragma unroll
            for (int i = 0; i < 8; i++)
#pragma unroll
                for (int j = 0; j < 8; j++) acc[i][j] += av[i]*bv[j];
        }
        __syncthreads();
    }
    float4 bb0 = *(const float4*)&bias[bn + tx*8];
    float4 bb1 = *(const float4*)&bias[bn + tx*8 + 4];
    float bv[8] = {bb0.x, bb0.y, bb0.z, bb0.w, bb1.x, bb1.y, bb1.z, bb1.w};
#pragma unroll
    for (int i = 0; i < 8; i++) {
        size_t row = (size_t)(bm + ty*8 + i);
        float4 o0, o1;
        o0.x = fmaxf(acc[i][0]+bv[0], 0.f); o0.y = fmaxf(acc[i][1]+bv[1], 0.f);
        o0.z = fmaxf(acc[i][2]+bv[2], 0.f); o0.w = fmaxf(acc[i][3]+bv[3], 0.f);
        o1.x = fmaxf(acc[i][4]+bv[4], 0.f); o1.y = fmaxf(acc[i][5]+bv[5], 0.f);
        o1.z = fmaxf(acc[i][6]+bv[6], 0.f); o1.w = fmaxf(acc[i][7]+bv[7], 0.f);
        *(float4*)&Y[row*N + bn + tx*8]     = o0;
        *(float4*)&Y[row*N + bn + tx*8 + 4] = o1;
    }
}

__global__ void maxpool_kernel(const float* __restrict__ Y, float* __restrict__ out,
                               int P, int ns, int C)
{
    int i = blockIdx.x*blockDim.x + threadIdx.x;
    if (i >= P*C) return;
    int p = i / C, c = i % C;
    const float* base = Y + (size_t)p*ns*C + c;
    float m = base[0];
    for (int n = 1; n < ns; n++) m = fmaxf(m, base[(size_t)n*C]);
    out[i] = m;
}

static inline int cdiv(int a, int b) { return (a + b - 1) / b; }

extern "C" void kernel_launch(void* const* d_in, const int* in_sizes, int n_in,
                              void* d_out, int out_size)
{
    (void)in_sizes; (void)n_in; (void)out_size;
    const float* pc  = (const float*)d_in[0];
    const float* w10 = (const float*)d_in[1],  *b10 = (const float*)d_in[2];
    const float* w11 = (const float*)d_in[3],  *b11 = (const float*)d_in[4];
    const float* w12 = (const float*)d_in[5],  *b12 = (const float*)d_in[6];
    const float* w20 = (const float*)d_in[7],  *b20 = (const float*)d_in[8];
    const float* w21 = (const float*)d_in[9],  *b21 = (const float*)d_in[10];
    const float* w22 = (const float*)d_in[11], *b22 = (const float*)d_in[12];
    const float* w30 = (const float*)d_in[13], *b30 = (const float*)d_in[14];
    const float* w31 = (const float*)d_in[15], *b31 = (const float*)d_in[16];
    const float* w32 = (const float*)d_in[17], *b32 = (const float*)d_in[18];
    const float* w40 = (const float*)d_in[19], *b40 = (const float*)d_in[20];
    const float* w41 = (const float*)d_in[21], *b41 = (const float*)d_in[22];
    const float* w42 = (const float*)d_in[23], *b42 = (const float*)d_in[24];

    float *nx1, *nx2, *nx3, *f1, *f2, *f3, *X0, *YA, *YB;
    int *fidx, *nidx;
    cudaGetSymbolAddress((void**)&nx1,  g_nx1);
    cudaGetSymbolAddress((void**)&nx2,  g_nx2);
    cudaGetSymbolAddress((void**)&nx3,  g_nx3);
    cudaGetSymbolAddress((void**)&f1,   g_f1);
    cudaGetSymbolAddress((void**)&f2,   g_f2);
    cudaGetSymbolAddress((void**)&f3,   g_f3);
    cudaGetSymbolAddress((void**)&X0,   g_X0);
    cudaGetSymbolAddress((void**)&YA,   g_YA);
    cudaGetSymbolAddress((void**)&YB,   g_YB);
    cudaGetSymbolAddress((void**)&fidx, g_fidx);
    cudaGetSymbolAddress((void**)&nidx, g_nidx);

    cudaFuncSetAttribute((const void*)fps1_bucket,
                         cudaFuncAttributeMaxDynamicSharedMemorySize, 65536);
    cudaFuncSetAttribute((const void*)sa1_kernel,
                         cudaFuncAttributeMaxDynamicSharedMemorySize, SA1_SMEM*4);

    float* out = (float*)d_out;
    float* nx4 = out;          // [4,256,3]
    float* f4  = out + 3072;   // [4,256,512]

    // Stage 1: 16384 -> 2048, r=0.2, ns=64
    fps1_bucket<<<NB, 1024, 65536>>>(pc, fidx);
    gather_xyz<<<cdiv(NB*2048*3,256),256>>>(pc, fidx, nx1, 2048, 16384, NB*2048*3);
    ball_query_kernel<<<cdiv(NB*2048*32,256),256>>>(pc, nx1, nidx, 2048, 16384, 64, 0.04f, NB*2048);
    sa1_kernel<<<NB*2048, 128, SA1_SMEM*4>>>(pc, nx1, nidx, w10,b10,w11,b11,w12,b12, f1, 0.2f);

    // Stage 2: 2048 -> 1024, r=0.4, ns=32, MLP 131->128->128->256
    fps_reg_kernel<512,4><<<NB, 512, 3*2048*4>>>(nx1, 1024, fidx);
    gather_xyz<<<cdiv(NB*1024*3,256),256>>>(nx1, fidx, nx2, 1024, 2048, NB*1024*3);
    ball_query_kernel<<<cdiv(NB*1024*32,256),256>>>(nx1, nx2, nidx, 1024, 2048, 32, 0.16f, NB*1024);
    group_kernel<<<cdiv(NB*1024*32*131,256),256>>>(nx1, nx2, nidx, f1, X0, 1024, 2048, 32, 128, 0.4f, NB*1024*32*131);
    gemm128<<<dim3(1, 1024), 256>>>(X0, w20, b20, YA, 131072, 128, 131);
    gemm128<<<dim3(1, 1024), 256>>>(YA, w21, b21, YB, 131072, 128, 128);
    gemm128<<<dim3(2, 1024), 256>>>(YB, w22, b22, YA, 131072, 256, 128);
    maxpool_kernel<<<cdiv(NB*1024*256,256),256>>>(YA, f2, NB*1024, 32, 256);

    // Stage 3: 1024 -> 512, r=0.6, ns=16, MLP 259->256->256->512
    fps_reg_kernel<256,4><<<NB, 256, 3*1024*4>>>(nx2, 512, fidx);
    gather_xyz<<<cdiv(NB*512*3,256),256>>>(nx2, fidx, nx3, 512, 1024, NB*512*3);
    ball_query_kernel<<<cdiv(NB*512*32,256),256>>>(nx2, nx3, nidx, 512, 1024, 16, 0.36f, NB*512);
    group_kernel<<<cdiv(NB*512*16*259,256),256>>>(nx2, nx3, nidx, f2, X0, 512, 1024, 16, 256, 0.6f, NB*512*16*259);
    gemm128<<<dim3(2, 256), 256>>>(X0, w30, b30, YA, 32768, 256, 259);
    gemm128<<<dim3(2, 256), 256>>>(YA, w31, b31, YB, 32768, 256, 256);
    gemm128<<<dim3(4, 256), 256>>>(YB, w32, b32, YA, 32768, 512, 256);
    maxpool_kernel<<<cdiv(NB*512*512,256),256>>>(YA, f3, NB*512, 16, 512);

    // Stage 4: 512 -> 256, r=1.2, ns=8, MLP 515->512->512->512
    fps_reg_kernel<128,4><<<NB, 128, 3*512*4>>>(nx3, 256, fidx);
    gather_xyz<<<cdiv(NB*256*3,256),256>>>(nx3, fidx, nx4, 256, 512, NB*256*3);
    ball_query_kernel<<<cdiv(NB*256*32,256),256>>>(nx3, nx4, nidx, 256, 512, 8, 1.44f, NB*256);
    group_kernel<<<cdiv(NB*256*8*515,256),256>>>(nx3, nx4, nidx, f3, X0, 256, 512, 8, 512, 1.2f, NB*256*8*515);
    gemm128<<<dim3(4, 64), 256>>>(X0, w40, b40, YA, 8192, 512, 515);
    gemm128<<<dim3(4, 64), 256>>>(YA, w41, b41, YB, 8192, 512, 512);
    gemm128<<<dim3(4, 64), 256>>>(YB, w42, b42, YA, 8192, 512, 512);
    maxpool_kernel<<<cdiv(NB*256*512,256),256>>>(YA, f4, NB*256, 8, 512);
}

// round 5
// speedup vs baseline: 1.5750x; 1.5750x over previous
#include <cuda_runtime.h>
#include <cstdint>

#define NB 4
typedef unsigned long long ull;

// ---------------- static device scratch ----------------
__device__ float g_nx1[NB*2048*3];
__device__ float g_nx2[NB*1024*3];
__device__ float g_nx3[NB*512*3];
__device__ float g_f1[NB*2048*128];
__device__ float g_f2[NB*1024*256];
__device__ float g_f3[NB*512*512];
__device__ int   g_fidx[NB*2048];
__device__ int   g_nidx[NB*2048*64];
__device__ float g_X0[17170432];
__device__ float g_YA[33554432];
__device__ float g_YB[16777216];
__device__ float4 g_pk4[NB*16384];
// FPS1 grid-sync slots (ping-pong by iteration parity; epoch-tagged keys)
__device__ ull g_keys[2][NB*16];

// ================== FPS stage 1: 16 CTAs per batch, manual grid sync ==================
// key = (distBits<<32) | (iter<<14) | (16383 - idx)  -> max-key == argmax(dist), first idx on tie
__global__ __launch_bounds__(1024)
void fps1_grid(const float* __restrict__ xyz, int* __restrict__ fidx)
{
    __shared__ ull  s_wk[32];
    __shared__ float s_c[3];

    const int blk = blockIdx.x;
    const int b = blk >> 4, c = blk & 15;
    const int t = threadIdx.x;
    const int lane = t & 31, w = t >> 5;
    const int idx = (c << 10) | t;                 // 0..16383
    const float* base = xyz + (size_t)b*16384*3;

    const float px = base[idx*3], py = base[idx*3+1], pz = base[idx*3+2];
    float dist = 1e10f;
    float cx = base[0], cy = base[1], cz = base[2];
    if (c == 0 && t == 0) fidx[(size_t)b*2048] = 0;

    for (int j = 1; j < 2048; j++) {
        float dx = px-cx, dy = py-cy, dz = pz-cz;
        float nd = fminf(dist, dx*dx + dy*dy + dz*dz);
        dist = nd;
        ull key = ((ull)__float_as_uint(nd) << 32) | ((ull)j << 14) | (ull)(16383 - idx);
#pragma unroll
        for (int o = 16; o; o >>= 1) {
            ull ok = __shfl_xor_sync(0xffffffffu, key, o);
            key = (ok > key) ? ok : key;
        }
        if (lane == 0) s_wk[w] = key;
        __syncthreads();
        if (w == 0) {
            ull k2 = s_wk[lane];
#pragma unroll
            for (int o = 16; o; o >>= 1) {
                ull ok = __shfl_xor_sync(0xffffffffu, k2, o);
                k2 = (ok > k2) ? ok : k2;
            }
            if (lane == 0)
                *((volatile ull*)&g_keys[j & 1][(b << 4) | c]) = k2;
            // poll peer CTAs (lanes 0..15), epoch check
            ull kk = 0;
            const unsigned em = (unsigned)j;
            for (;;) {
                if (lane < 16) kk = *((volatile ull*)&g_keys[j & 1][(b << 4) | lane]);
                bool okp = (lane >= 16) || ((unsigned)((kk >> 14) & 0x3FFFFu) == em);
                if (__all_sync(0xffffffffu, okp)) break;
            }
            if (lane >= 16) kk = 0;
#pragma unroll
            for (int o = 16; o; o >>= 1) {
                ull ok = __shfl_xor_sync(0xffffffffu, kk, o);
                kk = (ok > kk) ? ok : kk;
            }
            if (lane == 0) {
                int widx = 16383 - (int)(kk & 0x3FFFu);
                if (c == 0) fidx[(size_t)b*2048 + j] = widx;
                s_c[0] = base[widx*3]; s_c[1] = base[widx*3+1]; s_c[2] = base[widx*3+2];
            }
        }
        __syncthreads();
        cx = s_c[0]; cy = s_c[1]; cz = s_c[2];
    }
}

// ============ FPS stages 2-4: coords fully in registers ============
template<int BLK, int P>
__global__ __launch_bounds__(BLK)
void fps_reg_kernel(const float* __restrict__ xyz, int npoint, int* __restrict__ fidx)
{
    const int N = BLK * P;
    extern __shared__ float sm[];
    float* sx = sm; float* sy = sm + N; float* sz = sm + 2*N;
    __shared__ float rv[32];
    __shared__ int   ri[32];
    __shared__ float s_cx, s_cy, s_cz;

    const int b = blockIdx.x, t = threadIdx.x;
    const float* base = xyz + (size_t)b * N * 3;
    float px[P], py[P], pz[P], dst[P];
#pragma unroll
    for (int k = 0; k < P; k++) {
        int i = t + k*BLK;
        px[k] = base[i*3+0]; py[k] = base[i*3+1]; pz[k] = base[i*3+2];
        sx[i] = px[k]; sy[i] = py[k]; sz[i] = pz[k];
        dst[k] = 1e10f;
    }
    if (t == 0) {
        s_cx = px[0]; s_cy = py[0]; s_cz = pz[0];
        fidx[(size_t)b*npoint] = 0;
    }
    __syncthreads();

    for (int j = 1; j < npoint; j++) {
        const float cx = s_cx, cy = s_cy, cz = s_cz;
        float best = -1.0f; int bi = 0x7fffffff;
#pragma unroll
        for (int k = 0; k < P; k++) {
            float dx = px[k]-cx, dy = py[k]-cy, dz = pz[k]-cz;
            float nd = fminf(dst[k], dx*dx + dy*dy + dz*dz);
            dst[k] = nd;
            if (nd > best) { best = nd; bi = t + k*BLK; }
        }
#pragma unroll
        for (int off = 16; off; off >>= 1) {
            float ov = __shfl_down_sync(0xffffffffu, best, off);
            int   oi = __shfl_down_sync(0xffffffffu, bi,   off);
            if (ov > best || (ov == best && oi < bi)) { best = ov; bi = oi; }
        }
        int w = t >> 5;
        if ((t & 31) == 0) { rv[w] = best; ri[w] = bi; }
        __syncthreads();
        if (t < 32) {
            const int nw = BLK / 32;
            float v  = (t < nw) ? rv[t] : -1.0f;
            int   i2 = (t < nw) ? ri[t] : 0x7fffffff;
#pragma unroll
            for (int off = 16; off; off >>= 1) {
                float ov = __shfl_down_sync(0xffffffffu, v,  off);
                int   oi = __shfl_down_sync(0xffffffffu, i2, off);
                if (ov > v || (ov == v && oi < i2)) { v = ov; i2 = oi; }
            }
            if (t == 0) {
                fidx[(size_t)b*npoint + j] = i2;
                s_cx = sx[i2]; s_cy = sy[i2]; s_cz = sz[i2];
            }
        }
        __syncthreads();
    }
}

__global__ void gather_xyz(const float* __restrict__ xyz, const int* __restrict__ fidx,
                           float* __restrict__ nxyz, int S, int N, int total)
{
    int idx = blockIdx.x*blockDim.x + threadIdx.x;
    if (idx >= total) return;
    int b = idx / (S*3);
    int r = idx % (S*3);
    int s = r / 3, c = r % 3;
    nxyz[idx] = xyz[((size_t)b*N + fidx[b*S + s])*3 + c];
}

// ---- pack (x,y,z,|p|^2) for stage-1 ball query ----
__global__ void pack4_kernel(const float* __restrict__ xyz, float4* __restrict__ pk, int total)
{
    int i = blockIdx.x*blockDim.x + threadIdx.x;
    if (i >= total) return;
    float x = xyz[i*3+0], y = xyz[i*3+1], z = xyz[i*3+2];
    pk[i] = make_float4(x, y, z, (x*x + y*y) + z*z);
}

// ---- ball query on packed float4 (stage 1) ----
__global__ void ball_query4(const float4* __restrict__ pk, const float* __restrict__ nxyz,
                            int* __restrict__ nidx, int S, int N, int nsample,
                            float r2, int nwarps)
{
    int gw   = (blockIdx.x*blockDim.x + threadIdx.x) >> 5;
    int lane = threadIdx.x & 31;
    if (gw >= nwarps) return;
    int b = gw / S;
    const float4* xb = pk + (size_t)b * N;
    float nx = nxyz[gw*3+0], ny = nxyz[gw*3+1], nz = nxyz[gw*3+2];
    float sn = (nx*nx + ny*ny) + nz*nz;
    int* out = nidx + (size_t)gw * nsample;

    int cnt = 0, first = -1;
    for (int base = 0; base < N; base += 32) {
        int j = base + lane;
        float4 p = __ldg(&xb[j]);
        float dot = (nx*p.x + ny*p.y) + nz*p.z;
        bool in = ((sn + p.w) - 2.0f*dot) < r2;
        unsigned m = __ballot_sync(0xffffffffu, in);
        if (in) {
            int pos = cnt + __popc(m & ((1u << lane) - 1u));
            if (pos < nsample) out[pos] = j;
        }
        if (first < 0 && m) first = base + __ffs(m) - 1;
        cnt += __popc(m);
        if (cnt >= nsample) break;
    }
    for (int p = cnt + lane; p < nsample; p += 32) out[p] = first;
}

// ---- ball query (stages 2-4, SoA) ----
__global__ void ball_query_kernel(const float* __restrict__ xyz, const float* __restrict__ nxyz,
                                  int* __restrict__ nidx, int S, int N, int nsample,
                                  float r2, int nwarps)
{
    int gw   = (blockIdx.x*blockDim.x + threadIdx.x) >> 5;
    int lane = threadIdx.x & 31;
    if (gw >= nwarps) return;
    int b = gw / S;
    const float* xb = xyz + (size_t)b * N * 3;
    float nx = nxyz[gw*3+0], ny = nxyz[gw*3+1], nz = nxyz[gw*3+2];
    float sn = (nx*nx + ny*ny) + nz*nz;
    int* out = nidx + (size_t)gw * nsample;

    int cnt = 0, first = -1;
    for (int base = 0; base < N; base += 32) {
        int j = base + lane;
        bool in = false;
        if (j < N) {
            float x = xb[j*3+0], y = xb[j*3+1], z = xb[j*3+2];
            float sxx = (x*x + y*y) + z*z;
            float dot = (nx*x + ny*y) + nz*z;
            in = ((sn + sxx) - 2.0f*dot) < r2;
        }
        unsigned m = __ballot_sync(0xffffffffu, in);
        if (in) {
            int pos = cnt + __popc(m & ((1u << lane) - 1u));
            if (pos < nsample) out[pos] = j;
        }
        if (first < 0 && m) first = base + __ffs(m) - 1;
        cnt += __popc(m);
        if (cnt >= nsample) break;
    }
    for (int p = cnt + lane; p < nsample; p += 32) out[p] = first;
}

// ============ stage 1 fused: group + MLP(3->64->64->128) + maxpool ============
#define SA1_SMEM 12928
__global__ __launch_bounds__(128)
void sa1_kernel(const float* __restrict__ xyz, const float* __restrict__ nxyz,
                const int* __restrict__ nidx,
                const float* __restrict__ w0, const float* __restrict__ b0,
                const float* __restrict__ w1, const float* __restrict__ b1,
                const float* __restrict__ w2, const float* __restrict__ b2,
                float* __restrict__ feats, float radius)
{
    extern __shared__ float sm[];
    float* sW0 = sm;              // 192
    float* sB0 = sm + 192;        // 64
    float* sW1 = sm + 256;        // 4096
    float* sB1 = sm + 4352;       // 64
    float* sB2 = sm + 4416;       // 128
    float* sR  = sm + 4544;       // 192
    float* sH0 = sm + 4736;       // 64x64 transposed [c][n]
    float* sH1 = sm + 8832;       // 64x64 transposed [c][n]

    const int t = threadIdx.x;
    const int ctr = blockIdx.x;
    const int b = ctr >> 11;

    for (int i = t; i < 192;  i += 128) sW0[i] = w0[i];
    if (t < 64) { sB0[t] = b0[t]; sB1[t] = b1[t]; }
    for (int i = t; i < 4096; i += 128) sW1[i] = w1[i];
    sB2[t] = b2[t];
    if (t < 64) {
        int id = nidx[(size_t)ctr*64 + t];
        const float* p = xyz + ((size_t)(b << 14) + id)*3;
        sR[t*3+0] = (p[0] - nxyz[ctr*3+0]) / radius;
        sR[t*3+1] = (p[1] - nxyz[ctr*3+1]) / radius;
        sR[t*3+2] = (p[2] - nxyz[ctr*3+2]) / radius;
    }
    __syncthreads();

    {
        int n = t & 63, half = t >> 6;
        float rx = sR[n*3+0], ry = sR[n*3+1], rz = sR[n*3+2];
#pragma unroll 8
        for (int cc = 0; cc < 32; cc++) {
            int c = half*32 + cc;
            float v = sB0[c] + rx*sW0[c] + ry*sW0[64+c] + rz*sW0[128+c];
            sH0[c*64 + n] = fmaxf(v, 0.0f);
        }
    }
    __syncthreads();

    const int ng = t & 15, cg = t >> 4;
    float acc[32];

#pragma unroll
    for (int i = 0; i < 4; i++)
#pragma unroll
        for (int jj = 0; jj < 8; jj++) acc[i*8+jj] = sB1[8*cg + jj];
#pragma unroll 8
    for (int k = 0; k < 64; k++) {
        float4 a = *(const float4*)&sH0[k*64 + 4*ng];
        float4 u = *(const float4*)&sW1[k*64 + 8*cg];
        float4 v = *(const float4*)&sW1[k*64 + 8*cg + 4];
        float av[4] = {a.x, a.y, a.z, a.w};
        float bv[8] = {u.x, u.y, u.z, u.w, v.x, v.y, v.z, v.w};
#pragma unroll
        for (int i = 0; i < 4; i++)
#pragma unroll
            for (int jj = 0; jj < 8; jj++) acc[i*8+jj] += av[i]*bv[jj];
    }
#pragma unroll
    for (int jj = 0; jj < 8; jj++) {
        float4 o;
        o.x = fmaxf(acc[0*8+jj], 0.0f);
        o.y = fmaxf(acc[1*8+jj], 0.0f);
        o.z = fmaxf(acc[2*8+jj], 0.0f);
        o.w = fmaxf(acc[3*8+jj], 0.0f);
        *(float4*)&sH1[(8*cg+jj)*64 + 4*ng] = o;
    }
    __syncthreads();

#pragma unroll 1
    for (int pass = 0; pass < 2; pass++) {
        int c0 = pass*64 + 8*cg;
#pragma unroll
        for (int i = 0; i < 4; i++)
#pragma unroll
            for (int jj = 0; jj < 8; jj++) acc[i*8+jj] = sB2[c0 + jj];
#pragma unroll 4
        for (int k = 0; k < 64; k++) {
            float4 a = *(const float4*)&sH1[k*64 + 4*ng];
            float4 u = *(const float4*)&w2[k*128 + c0];
            float4 v = *(const float4*)&w2[k*128 + c0 + 4];
            float av[4] = {a.x, a.y, a.z, a.w};
            float bv[8] = {u.x, u.y, u.z, u.w, v.x, v.y, v.z, v.w};
#pragma unroll
            for (int i = 0; i < 4; i++)
#pragma unroll
                for (int jj = 0; jj < 8; jj++) acc[i*8+jj] += av[i]*bv[jj];
        }
#pragma unroll
        for (int jj = 0; jj < 8; jj++) {
            float m = fmaxf(fmaxf(fmaxf(acc[0*8+jj], 0.0f), fmaxf(acc[1*8+jj], 0.0f)),
                            fmaxf(fmaxf(acc[2*8+jj], 0.0f), fmaxf(acc[3*8+jj], 0.0f)));
#pragma unroll
            for (int off = 8; off; off >>= 1)
                m = fmaxf(m, __shfl_xor_sync(0xffffffffu, m, off));
            if (ng == 0) feats[(size_t)ctr*128 + c0 + jj] = m;
        }
    }
}

__global__ void group_kernel(const float* __restrict__ xyz, const float* __restrict__ nxyz,
                             const int* __restrict__ nidx, const float* __restrict__ feats,
                             float* __restrict__ X0, int S, int N, int ns, int C,
                             float radius, int total)
{
    int idx = blockIdx.x*blockDim.x + threadIdx.x;
    if (idx >= total) return;
    int Cin = 3 + C;
    int row = idx / Cin, c = idx % Cin;
    int b = row / (S*ns);
    int r = row % (S*ns);
    int s = r / ns;
    int id = nidx[row];
    if (c < 3) {
        X0[idx] = (xyz[((size_t)b*N + id)*3 + c] - nxyz[((size_t)b*S + s)*3 + c]) / radius;
    } else {
        X0[idx] = feats[((size_t)b*N + id)*C + (c - 3)];
    }
}

// ============ fp32 GEMM + bias + relu: 128x128 tile, 8x8 micro, reg double-buffer ============
__global__ __launch_bounds__(256)
void gemm128(const float* __restrict__ A, const float* __restrict__ W,
             const float* __restrict__ bias, float* __restrict__ Y,
             int M, int N, int K)
{
    __shared__ __align__(16) float As[8][128];
    __shared__ __align__(16) float Bs[8][128];
    const int bm = blockIdx.y * 128;
    const int bn = blockIdx.x * 128;
    const int t  = threadIdx.x;
    const int ty = t >> 4, tx = t & 15;
    float acc[8][8];
#pragma unroll
    for (int i = 0; i < 8; i++)
#pragma unroll
        for (int j = 0; j < 8; j++) acc[i][j] = 0.0f;

    const int abr = t >> 5;
    const int abc = (t & 31) * 4;

    float ra[4]; float4 rb;
#pragma unroll
    for (int q = 0; q < 4; q++) {
        int e = t*4 + q;
        int ar = e >> 3, ac = e & 7;
        ra[q] = (ac < K) ? A[(size_t)(bm + ar)*K + ac] : 0.0f;
    }
    rb = (abr < K) ? *(const float4*)&W[(size_t)abr*N + bn + abc]
                   : make_float4(0.f,0.f,0.f,0.f);

    for (int k0 = 0; k0 < K; k0 += 8) {
#pragma unroll
        for (int q = 0; q < 4; q++) {
            int e = t*4 + q;
            As[e & 7][e >> 3] = ra[q];
        }
        *(float4*)&Bs[abr][abc] = rb;
        __syncthreads();
        if (k0 + 8 < K) {
#pragma unroll
            for (int q = 0; q < 4; q++) {
                int e = t*4 + q;
                int ar = e >> 3, ac = e & 7;
                int kk = k0 + 8 + ac;
                ra[q] = (kk < K) ? A[(size_t)(bm + ar)*K + kk] : 0.0f;
            }
            int kk = k0 + 8 + abr;
            rb = (kk < K) ? *(const float4*)&W[(size_t)kk*N + bn + abc]
                          : make_float4(0.f,0.f,0.f,0.f);
        }
#pragma unroll
        for (int kk = 0; kk < 8; kk++) {
            float4 a0 = *(const float4*)&As[kk][ty*8];
            float4 a1 = *(const float4*)&As[kk][ty*8 + 4];
            float4 b0 = *(const float4*)&Bs[kk][tx*8];
            float4 b1 = *(const float4*)&Bs[kk][tx*8 + 4];
            float av[8] = {a0.x, a0.y, a0.z, a0.w, a1.x, a1.y, a1.z, a1.w};
            float bv[8] = {b0.x, b0.y, b0.z, b0.w, b1.x, b1.y, b1.z, b1.w};
#pragma unroll
            for (int i = 0; i < 8; i++)
#pragma unroll
                for (int j = 0; j < 8; j++) acc[i][j] += av[i]*bv[j];
        }
        __syncthreads();
    }
    float4 bb0 = *(const float4*)&bias[bn + tx*8];
    float4 bb1 = *(const float4*)&bias[bn + tx*8 + 4];
    float bv[8] = {bb0.x, bb0.y, bb0.z, bb0.w, bb1.x, bb1.y, bb1.z, bb1.w};
#pragma unroll
    for (int i = 0; i < 8; i++) {
        size_t row = (size_t)(bm + ty*8 + i);
        float4 o0, o1;
        o0.x = fmaxf(acc[i][0]+bv[0], 0.f); o0.y = fmaxf(acc[i][1]+bv[1], 0.f);
        o0.z = fmaxf(acc[i][2]+bv[2], 0.f); o0.w = fmaxf(acc[i][3]+bv[3], 0.f);
        o1.x = fmaxf(acc[i][4]+bv[4], 0.f); o1.y = fmaxf(acc[i][5]+bv[5], 0.f);
        o1.z = fmaxf(acc[i][6]+bv[6], 0.f); o1.w = fmaxf(acc[i][7]+bv[7], 0.f);
        *(float4*)&Y[row*N + bn + tx*8]     = o0;
        *(float4*)&Y[row*N + bn + tx*8 + 4] = o1;
    }
}

__global__ void maxpool_kernel(const float* __restrict__ Y, float* __restrict__ out,
                               int P, int ns, int C)
{
    int i = blockIdx.x*blockDim.x + threadIdx.x;
    if (i >= P*C) return;
    int p = i / C, c = i % C;
    const float* base = Y + (size_t)p*ns*C + c;
    float m = base[0];
    for (int n = 1; n < ns; n++) m = fmaxf(m, base[(size_t)n*C]);
    out[i] = m;
}

static inline int cdiv(int a, int b) { return (a + b - 1) / b; }

extern "C" void kernel_launch(void* const* d_in, const int* in_sizes, int n_in,
                              void* d_out, int out_size)
{
    (void)in_sizes; (void)n_in; (void)out_size;
    const float* pc  = (const float*)d_in[0];
    const float* w10 = (const float*)d_in[1],  *b10 = (const float*)d_in[2];
    const float* w11 = (const float*)d_in[3],  *b11 = (const float*)d_in[4];
    const float* w12 = (const float*)d_in[5],  *b12 = (const float*)d_in[6];
    const float* w20 = (const float*)d_in[7],  *b20 = (const float*)d_in[8];
    const float* w21 = (const float*)d_in[9],  *b21 = (const float*)d_in[10];
    const float* w22 = (const float*)d_in[11], *b22 = (const float*)d_in[12];
    const float* w30 = (const float*)d_in[13], *b30 = (const float*)d_in[14];
    const float* w31 = (const float*)d_in[15], *b31 = (const float*)d_in[16];
    const float* w32 = (const float*)d_in[17], *b32 = (const float*)d_in[18];
    const float* w40 = (const float*)d_in[19], *b40 = (const float*)d_in[20];
    const float* w41 = (const float*)d_in[21], *b41 = (const float*)d_in[22];
    const float* w42 = (const float*)d_in[23], *b42 = (const float*)d_in[24];

    float *nx1, *nx2, *nx3, *f1, *f2, *f3, *X0, *YA, *YB;
    float4 *pk4;
    int *fidx, *nidx;
    cudaGetSymbolAddress((void**)&nx1,  g_nx1);
    cudaGetSymbolAddress((void**)&nx2,  g_nx2);
    cudaGetSymbolAddress((void**)&nx3,  g_nx3);
    cudaGetSymbolAddress((void**)&f1,   g_f1);
    cudaGetSymbolAddress((void**)&f2,   g_f2);
    cudaGetSymbolAddress((void**)&f3,   g_f3);
    cudaGetSymbolAddress((void**)&X0,   g_X0);
    cudaGetSymbolAddress((void**)&YA,   g_YA);
    cudaGetSymbolAddress((void**)&YB,   g_YB);
    cudaGetSymbolAddress((void**)&fidx, g_fidx);
    cudaGetSymbolAddress((void**)&nidx, g_nidx);
    cudaGetSymbolAddress((void**)&pk4,  g_pk4);

    cudaFuncSetAttribute((const void*)sa1_kernel,
                         cudaFuncAttributeMaxDynamicSharedMemorySize, SA1_SMEM*4);

    float* out = (float*)d_out;
    float* nx4 = out;          // [4,256,3]
    float* f4  = out + 3072;   // [4,256,512]

    // Stage 1: 16384 -> 2048, r=0.2, ns=64
    pack4_kernel<<<cdiv(NB*16384,256),256>>>(pc, pk4, NB*16384);
    fps1_grid<<<NB*16, 1024>>>(pc, fidx);
    gather_xyz<<<cdiv(NB*2048*3,256),256>>>(pc, fidx, nx1, 2048, 16384, NB*2048*3);
    ball_query4<<<cdiv(NB*2048*32,256),256>>>(pk4, nx1, nidx, 2048, 16384, 64, 0.04f, NB*2048);
    sa1_kernel<<<NB*2048, 128, SA1_SMEM*4>>>(pc, nx1, nidx, w10,b10,w11,b11,w12,b12, f1, 0.2f);

    // Stage 2: 2048 -> 1024, r=0.4, ns=32, MLP 131->128->128->256
    fps_reg_kernel<512,4><<<NB, 512, 3*2048*4>>>(nx1, 1024, fidx);
    gather_xyz<<<cdiv(NB*1024*3,256),256>>>(nx1, fidx, nx2, 1024, 2048, NB*1024*3);
    ball_query_kernel<<<cdiv(NB*1024*32,256),256>>>(nx1, nx2, nidx, 1024, 2048, 32, 0.16f, NB*1024);
    group_kernel<<<cdiv(NB*1024*32*131,256),256>>>(nx1, nx2, nidx, f1, X0, 1024, 2048, 32, 128, 0.4f, NB*1024*32*131);
    gemm128<<<dim3(1, 1024), 256>>>(X0, w20, b20, YA, 131072, 128, 131);
    gemm128<<<dim3(1, 1024), 256>>>(YA, w21, b21, YB, 131072, 128, 128);
    gemm128<<<dim3(2, 1024), 256>>>(YB, w22, b22, YA, 131072, 256, 128);
    maxpool_kernel<<<cdiv(NB*1024*256,256),256>>>(YA, f2, NB*1024, 32, 256);

    // Stage 3: 1024 -> 512, r=0.6, ns=16, MLP 259->256->256->512
    fps_reg_kernel<256,4><<<NB, 256, 3*1024*4>>>(nx2, 512, fidx);
    gather_xyz<<<cdiv(NB*512*3,256),256>>>(nx2, fidx, nx3, 512, 1024, NB*512*3);
    ball_query_kernel<<<cdiv(NB*512*32,256),256>>>(nx2, nx3, nidx, 512, 1024, 16, 0.36f, NB*512);
    group_kernel<<<cdiv(NB*512*16*259,256),256>>>(nx2, nx3, nidx, f2, X0, 512, 1024, 16, 256, 0.6f, NB*512*16*259);
    gemm128<<<dim3(2, 256), 256>>>(X0, w30, b30, YA, 32768, 256, 259);
    gemm128<<<dim3(2, 256), 256>>>(YA, w31, b31, YB, 32768, 256, 256);
    gemm128<<<dim3(4, 256), 256>>>(YB, w32, b32, YA, 32768, 512, 256);
    maxpool_kernel<<<cdiv(NB*512*512,256),256>>>(YA, f3, NB*512, 16, 512);

    // Stage 4: 512 -> 256, r=1.2, ns=8, MLP 515->512->512->512
    fps_reg_kernel<128,4><<<NB, 128, 3*512*4>>>(nx3, 256, fidx);
    gather_xyz<<<cdiv(NB*256*3,256),256>>>(nx3, fidx, nx4, 256, 512, NB*256*3);
    ball_query_kernel<<<cdiv(NB*256*32,256),256>>>(nx3, nx4, nidx, 256, 512, 8, 1.44f, NB*256);
    group_kernel<<<cdiv(NB*256*8*515,256),256>>>(nx3, nx4, nidx, f3, X0, 256, 512, 8, 512, 1.2f, NB*256*8*515);
    gemm128<<<dim3(4, 64), 256>>>(X0, w40, b40, YA, 8192, 512, 515);
    gemm128<<<dim3(4, 64), 256>>>(YA, w41, b41, YB, 8192, 512, 512);
    gemm128<<<dim3(4, 64), 256>>>(YB, w42, b42, YA, 8192, 512, 512);
    maxpool_kernel<<<cdiv(NB*256*512,256),256>>>(YA, f4, NB*256, 8, 512);
}

// round 6
// speedup vs baseline: 1.6832x; 1.0687x over previous
#include <cuda_runtime.h>
#include <cstdint>

#define NB 4
typedef unsigned long long ull;

// ---------------- static device scratch ----------------
__device__ float g_nx1[NB*2048*3];
__device__ float g_nx2[NB*1024*3];
__device__ float g_nx3[NB*512*3];
__device__ float g_f1[NB*2048*128];
__device__ float g_f2[NB*1024*256];
__device__ float g_f3[NB*512*512];
__device__ int   g_fidx[NB*2048];
__device__ int   g_nidx[NB*2048*64];
__device__ float g_X0[17170432];
__device__ float g_YA[33554432];
__device__ float g_YB[16777216];
__device__ float4 g_pk4[NB*16384];

__device__ __forceinline__ uint32_t smem_u32(const void* p) {
    uint32_t a;
    asm("{ .reg .u64 t; cvta.to.shared.u64 t, %1; cvt.u32.u64 %0, t; }" : "=r"(a) : "l"(p));
    return a;
}
__device__ __forceinline__ ull ld_dsmem_u64(uint32_t laddr, uint32_t rank) {
    uint32_t r; ull v;
    asm volatile("mapa.shared::cluster.u32 %0, %1, %2;" : "=r"(r) : "r"(laddr), "r"(rank));
    asm volatile("ld.shared::cluster.b64 %0, [%1];" : "=l"(v) : "r"(r));
    return v;
}

// ================== FPS stage 1: 8-CTA cluster per batch, DSMEM key exchange ==================
#define CLU 8
__global__ __launch_bounds__(1024) __cluster_dims__(CLU, 1, 1)
void fps1_cluster(const float* __restrict__ xyz, int* __restrict__ fidx)
{
    __shared__ ull  s_wk[32];
    __shared__ ull  s_key[2];     // own CTA key, ping-pong by iter parity
    __shared__ float s_c[3];

    const int t = threadIdx.x, lane = t & 31, w = t >> 5;
    uint32_t rank; asm("mov.u32 %0, %%cluster_ctarank;" : "=r"(rank));
    const int b = blockIdx.x / CLU;
    const float* base = xyz + (size_t)b*16384*3;

    const int i0 = (int)rank*2048 + t;
    const int i1 = i0 + 1024;
    const float px0 = base[i0*3], py0 = base[i0*3+1], pz0 = base[i0*3+2];
    const float px1 = base[i1*3], py1 = base[i1*3+1], pz1 = base[i1*3+2];
    float d0 = 1e10f, d1 = 1e10f;
    float cx = base[0], cy = base[1], cz = base[2];
    if (rank == 0 && t == 0) fidx[(size_t)b*2048] = 0;
    const uint32_t keyAddr = smem_u32(&s_key[0]);

    for (int j = 1; j < 2048; j++) {
        const int p = j & 1;
        float dx = px0-cx, dy = py0-cy, dz = pz0-cz;
        float n0 = fminf(d0, dx*dx + dy*dy + dz*dz); d0 = n0;
        dx = px1-cx; dy = py1-cy; dz = pz1-cz;
        float n1 = fminf(d1, dx*dx + dy*dy + dz*dz); d1 = n1;
        ull k0 = ((ull)__float_as_uint(n0) << 32) | (ull)(16383 - i0);
        ull k1 = ((ull)__float_as_uint(n1) << 32) | (ull)(16383 - i1);
        ull key = (k1 > k0) ? k1 : k0;
#pragma unroll
        for (int o = 16; o; o >>= 1) {
            ull ok = __shfl_xor_sync(0xffffffffu, key, o);
            key = (ok > key) ? ok : key;
        }
        if (lane == 0) s_wk[w] = key;
        __syncthreads();
        if (w == 0) {
            ull k2 = s_wk[lane];
#pragma unroll
            for (int o = 16; o; o >>= 1) {
                ull ok = __shfl_xor_sync(0xffffffffu, k2, o);
                k2 = (ok > k2) ? ok : k2;
            }
            if (lane == 0) s_key[p] = k2;
        }
        asm volatile("barrier.cluster.arrive.aligned;" ::: "memory");
        asm volatile("barrier.cluster.wait.aligned;"   ::: "memory");
        if (w == 0) {
            ull kk = (lane < CLU) ? ld_dsmem_u64(keyAddr + p*8, (uint32_t)lane) : 0;
#pragma unroll
            for (int o = 16; o; o >>= 1) {
                ull ok = __shfl_xor_sync(0xffffffffu, kk, o);
                kk = (ok > kk) ? ok : kk;
            }
            if (lane == 0) {
                int widx = 16383 - (int)(kk & 0x3FFFu);
                if (rank == 0) fidx[(size_t)b*2048 + j] = widx;
                s_c[0] = base[widx*3]; s_c[1] = base[widx*3+1]; s_c[2] = base[widx*3+2];
            }
        }
        __syncthreads();
        cx = s_c[0]; cy = s_c[1]; cz = s_c[2];
    }
}

// ============ FPS stages 2-4: coords fully in registers ============
template<int BLK, int P>
__global__ __launch_bounds__(BLK)
void fps_reg_kernel(const float* __restrict__ xyz, int npoint, int* __restrict__ fidx)
{
    const int N = BLK * P;
    extern __shared__ float sm[];
    float* sx = sm; float* sy = sm + N; float* sz = sm + 2*N;
    __shared__ float rv[32];
    __shared__ int   ri[32];
    __shared__ float s_cx, s_cy, s_cz;

    const int b = blockIdx.x, t = threadIdx.x;
    const float* base = xyz + (size_t)b * N * 3;
    float px[P], py[P], pz[P], dst[P];
#pragma unroll
    for (int k = 0; k < P; k++) {
        int i = t + k*BLK;
        px[k] = base[i*3+0]; py[k] = base[i*3+1]; pz[k] = base[i*3+2];
        sx[i] = px[k]; sy[i] = py[k]; sz[i] = pz[k];
        dst[k] = 1e10f;
    }
    if (t == 0) {
        s_cx = px[0]; s_cy = py[0]; s_cz = pz[0];
        fidx[(size_t)b*npoint] = 0;
    }
    __syncthreads();

    for (int j = 1; j < npoint; j++) {
        const float cx = s_cx, cy = s_cy, cz = s_cz;
        float best = -1.0f; int bi = 0x7fffffff;
#pragma unroll
        for (int k = 0; k < P; k++) {
            float dx = px[k]-cx, dy = py[k]-cy, dz = pz[k]-cz;
            float nd = fminf(dst[k], dx*dx + dy*dy + dz*dz);
            dst[k] = nd;
            if (nd > best) { best = nd; bi = t + k*BLK; }
        }
#pragma unroll
        for (int off = 16; off; off >>= 1) {
            float ov = __shfl_down_sync(0xffffffffu, best, off);
            int   oi = __shfl_down_sync(0xffffffffu, bi,   off);
            if (ov > best || (ov == best && oi < bi)) { best = ov; bi = oi; }
        }
        int w = t >> 5;
        if ((t & 31) == 0) { rv[w] = best; ri[w] = bi; }
        __syncthreads();
        if (t < 32) {
            const int nw = BLK / 32;
            float v  = (t < nw) ? rv[t] : -1.0f;
            int   i2 = (t < nw) ? ri[t] : 0x7fffffff;
#pragma unroll
            for (int off = 16; off; off >>= 1) {
                float ov = __shfl_down_sync(0xffffffffu, v,  off);
                int   oi = __shfl_down_sync(0xffffffffu, i2, off);
                if (ov > v || (ov == v && oi < i2)) { v = ov; i2 = oi; }
            }
            if (t == 0) {
                fidx[(size_t)b*npoint + j] = i2;
                s_cx = sx[i2]; s_cy = sy[i2]; s_cz = sz[i2];
            }
        }
        __syncthreads();
    }
}

__global__ void gather_xyz(const float* __restrict__ xyz, const int* __restrict__ fidx,
                           float* __restrict__ nxyz, int S, int N, int total)
{
    int idx = blockIdx.x*blockDim.x + threadIdx.x;
    if (idx >= total) return;
    int b = idx / (S*3);
    int r = idx % (S*3);
    int s = r / 3, c = r % 3;
    nxyz[idx] = xyz[((size_t)b*N + fidx[b*S + s])*3 + c];
}

__global__ void pack4_kernel(const float* __restrict__ xyz, float4* __restrict__ pk, int total)
{
    int i = blockIdx.x*blockDim.x + threadIdx.x;
    if (i >= total) return;
    float x = xyz[i*3+0], y = xyz[i*3+1], z = xyz[i*3+2];
    pk[i] = make_float4(x, y, z, (x*x + y*y) + z*z);
}

__global__ void ball_query4(const float4* __restrict__ pk, const float* __restrict__ nxyz,
                            int* __restrict__ nidx, int S, int N, int nsample,
                            float r2, int nwarps)
{
    int gw   = (blockIdx.x*blockDim.x + threadIdx.x) >> 5;
    int lane = threadIdx.x & 31;
    if (gw >= nwarps) return;
    int b = gw / S;
    const float4* xb = pk + (size_t)b * N;
    float nx = nxyz[gw*3+0], ny = nxyz[gw*3+1], nz = nxyz[gw*3+2];
    float sn = (nx*nx + ny*ny) + nz*nz;
    int* out = nidx + (size_t)gw * nsample;

    int cnt = 0, first = -1;
    for (int base = 0; base < N; base += 32) {
        int j = base + lane;
        float4 p = __ldg(&xb[j]);
        float dot = (nx*p.x + ny*p.y) + nz*p.z;
        bool in = ((sn + p.w) - 2.0f*dot) < r2;
        unsigned m = __ballot_sync(0xffffffffu, in);
        if (in) {
            int pos = cnt + __popc(m & ((1u << lane) - 1u));
            if (pos < nsample) out[pos] = j;
        }
        if (first < 0 && m) first = base + __ffs(m) - 1;
        cnt += __popc(m);
        if (cnt >= nsample) break;
    }
    for (int p = cnt + lane; p < nsample; p += 32) out[p] = first;
}

__global__ void ball_query_kernel(const float* __restrict__ xyz, const float* __restrict__ nxyz,
                                  int* __restrict__ nidx, int S, int N, int nsample,
                                  float r2, int nwarps)
{
    int gw   = (blockIdx.x*blockDim.x + threadIdx.x) >> 5;
    int lane = threadIdx.x & 31;
    if (gw >= nwarps) return;
    int b = gw / S;
    const float* xb = xyz + (size_t)b * N * 3;
    float nx = nxyz[gw*3+0], ny = nxyz[gw*3+1], nz = nxyz[gw*3+2];
    float sn = (nx*nx + ny*ny) + nz*nz;
    int* out = nidx + (size_t)gw * nsample;

    int cnt = 0, first = -1;
    for (int base = 0; base < N; base += 32) {
        int j = base + lane;
        bool in = false;
        if (j < N) {
            float x = xb[j*3+0], y = xb[j*3+1], z = xb[j*3+2];
            float sxx = (x*x + y*y) + z*z;
            float dot = (nx*x + ny*y) + nz*z;
            in = ((sn + sxx) - 2.0f*dot) < r2;
        }
        unsigned m = __ballot_sync(0xffffffffu, in);
        if (in) {
            int pos = cnt + __popc(m & ((1u << lane) - 1u));
            if (pos < nsample) out[pos] = j;
        }
        if (first < 0 && m) first = base + __ffs(m) - 1;
        cnt += __popc(m);
        if (cnt >= nsample) break;
    }
    for (int p = cnt + lane; p < nsample; p += 32) out[p] = first;
}

// ============ stage 1 fused: group + MLP(3->64->64->128) + maxpool ============
#define SA1_SMEM 12928
__global__ __launch_bounds__(128)
void sa1_kernel(const float* __restrict__ xyz, const float* __restrict__ nxyz,
                const int* __restrict__ nidx,
                const float* __restrict__ w0, const float* __restrict__ b0,
                const float* __restrict__ w1, const float* __restrict__ b1,
                const float* __restrict__ w2, const float* __restrict__ b2,
                float* __restrict__ feats, float radius)
{
    extern __shared__ float sm[];
    float* sW0 = sm;              // 192
    float* sB0 = sm + 192;        // 64
    float* sW1 = sm + 256;        // 4096
    float* sB1 = sm + 4352;       // 64
    float* sB2 = sm + 4416;       // 128
    float* sR  = sm + 4544;       // 192
    float* sH0 = sm + 4736;       // 64x64 transposed [c][n]
    float* sH1 = sm + 8832;       // 64x64 transposed [c][n]

    const int t = threadIdx.x;
    const int ctr = blockIdx.x;
    const int b = ctr >> 11;

    for (int i = t; i < 192;  i += 128) sW0[i] = w0[i];
    if (t < 64) { sB0[t] = b0[t]; sB1[t] = b1[t]; }
    for (int i = t; i < 4096; i += 128) sW1[i] = w1[i];
    sB2[t] = b2[t];
    if (t < 64) {
        int id = nidx[(size_t)ctr*64 + t];
        const float* p = xyz + ((size_t)(b << 14) + id)*3;
        sR[t*3+0] = (p[0] - nxyz[ctr*3+0]) / radius;
        sR[t*3+1] = (p[1] - nxyz[ctr*3+1]) / radius;
        sR[t*3+2] = (p[2] - nxyz[ctr*3+2]) / radius;
    }
    __syncthreads();

    {
        int n = t & 63, half = t >> 6;
        float rx = sR[n*3+0], ry = sR[n*3+1], rz = sR[n*3+2];
#pragma unroll 8
        for (int cc = 0; cc < 32; cc++) {
            int c = half*32 + cc;
            float v = sB0[c] + rx*sW0[c] + ry*sW0[64+c] + rz*sW0[128+c];
            sH0[c*64 + n] = fmaxf(v, 0.0f);
        }
    }
    __syncthreads();

    const int ng = t & 15, cg = t >> 4;
    float acc[32];

#pragma unroll
    for (int i = 0; i < 4; i++)
#pragma unroll
        for (int jj = 0; jj < 8; jj++) acc[i*8+jj] = sB1[8*cg + jj];
#pragma unroll 8
    for (int k = 0; k < 64; k++) {
        float4 a = *(const float4*)&sH0[k*64 + 4*ng];
        float4 u = *(const float4*)&sW1[k*64 + 8*cg];
        float4 v = *(const float4*)&sW1[k*64 + 8*cg + 4];
        float av[4] = {a.x, a.y, a.z, a.w};
        float bv[8] = {u.x, u.y, u.z, u.w, v.x, v.y, v.z, v.w};
#pragma unroll
        for (int i = 0; i < 4; i++)
#pragma unroll
            for (int jj = 0; jj < 8; jj++) acc[i*8+jj] += av[i]*bv[jj];
    }
#pragma unroll
    for (int jj = 0; jj < 8; jj++) {
        float4 o;
        o.x = fmaxf(acc[0*8+jj], 0.0f);
        o.y = fmaxf(acc[1*8+jj], 0.0f);
        o.z = fmaxf(acc[2*8+jj], 0.0f);
        o.w = fmaxf(acc[3*8+jj], 0.0f);
        *(float4*)&sH1[(8*cg+jj)*64 + 4*ng] = o;
    }
    __syncthreads();

#pragma unroll 1
    for (int pass = 0; pass < 2; pass++) {
        int c0 = pass*64 + 8*cg;
#pragma unroll
        for (int i = 0; i < 4; i++)
#pragma unroll
            for (int jj = 0; jj < 8; jj++) acc[i*8+jj] = sB2[c0 + jj];
#pragma unroll 4
        for (int k = 0; k < 64; k++) {
            float4 a = *(const float4*)&sH1[k*64 + 4*ng];
            float4 u = *(const float4*)&w2[k*128 + c0];
            float4 v = *(const float4*)&w2[k*128 + c0 + 4];
            float av[4] = {a.x, a.y, a.z, a.w};
            float bv[8] = {u.x, u.y, u.z, u.w, v.x, v.y, v.z, v.w};
#pragma unroll
            for (int i = 0; i < 4; i++)
#pragma unroll
                for (int jj = 0; jj < 8; jj++) acc[i*8+jj] += av[i]*bv[jj];
        }
#pragma unroll
        for (int jj = 0; jj < 8; jj++) {
            float m = fmaxf(fmaxf(fmaxf(acc[0*8+jj], 0.0f), fmaxf(acc[1*8+jj], 0.0f)),
                            fmaxf(fmaxf(acc[2*8+jj], 0.0f), fmaxf(acc[3*8+jj], 0.0f)));
#pragma unroll
            for (int off = 8; off; off >>= 1)
                m = fmaxf(m, __shfl_xor_sync(0xffffffffu, m, off));
            if (ng == 0) feats[(size_t)ctr*128 + c0 + jj] = m;
        }
    }
}

__global__ void group_kernel(const float* __restrict__ xyz, const float* __restrict__ nxyz,
                             const int* __restrict__ nidx, const float* __restrict__ feats,
                             float* __restrict__ X0, int S, int N, int ns, int C,
                             float radius, int total)
{
    int idx = blockIdx.x*blockDim.x + threadIdx.x;
    if (idx >= total) return;
    int Cin = 3 + C;
    int row = idx / Cin, c = idx % Cin;
    int b = row / (S*ns);
    int r = row % (S*ns);
    int s = r / ns;
    int id = nidx[row];
    if (c < 3) {
        X0[idx] = (xyz[((size_t)b*N + id)*3 + c] - nxyz[((size_t)b*S + s)*3 + c]) / radius;
    } else {
        X0[idx] = feats[((size_t)b*N + id)*C + (c - 3)];
    }
}

// ============ fp32 GEMM + bias + relu: 128x128 tile, 8x8 micro, reg double-buffer ============
__global__ __launch_bounds__(256)
void gemm128(const float* __restrict__ A, const float* __restrict__ W,
             const float* __restrict__ bias, float* __restrict__ Y,
             int M, int N, int K)
{
    __shared__ __align__(16) float As[8][128];
    __shared__ __align__(16) float Bs[8][128];
    const int bm = blockIdx.y * 128;
    const int bn = blockIdx.x * 128;
    const int t  = threadIdx.x;
    const int ty = t >> 4, tx = t & 15;
    float acc[8][8];
#pragma unroll
    for (int i = 0; i < 8; i++)
#pragma unroll
        for (int j = 0; j < 8; j++) acc[i][j] = 0.0f;

    const int abr = t >> 5;
    const int abc = (t & 31) * 4;

    float ra[4]; float4 rb;
#pragma unroll
    for (int q = 0; q < 4; q++) {
        int e = t*4 + q;
        int ar = e >> 3, ac = e & 7;
        ra[q] = (ac < K) ? A[(size_t)(bm + ar)*K + ac] : 0.0f;
    }
    rb = (abr < K) ? *(const float4*)&W[(size_t)abr*N + bn + abc]
                   : make_float4(0.f,0.f,0.f,0.f);

    for (int k0 = 0; k0 < K; k0 += 8) {
#pragma unroll
        for (int q = 0; q < 4; q++) {
            int e = t*4 + q;
            As[e & 7][e >> 3] = ra[q];
        }
        *(float4*)&Bs[abr][abc] = rb;
        __syncthreads();
        if (k0 + 8 < K) {
#pragma unroll
            for (int q = 0; q < 4; q++) {
                int e = t*4 + q;
                int ar = e >> 3, ac = e & 7;
                int kk = k0 + 8 + ac;
                ra[q] = (kk < K) ? A[(size_t)(bm + ar)*K + kk] : 0.0f;
            }
            int kk = k0 + 8 + abr;
            rb = (kk < K) ? *(const float4*)&W[(size_t)kk*N + bn + abc]
                          : make_float4(0.f,0.f,0.f,0.f);
        }
#pragma unroll
        for (int kk = 0; kk < 8; kk++) {
            float4 a0 = *(const float4*)&As[kk][ty*8];
            float4 a1 = *(const float4*)&As[kk][ty*8 + 4];
            float4 b0 = *(const float4*)&Bs[kk][tx*8];
            float4 b1 = *(const float4*)&Bs[kk][tx*8 + 4];
            float av[8] = {a0.x, a0.y, a0.z, a0.w, a1.x, a1.y, a1.z, a1.w};
            float bv[8] = {b0.x, b0.y, b0.z, b0.w, b1.x, b1.y, b1.z, b1.w};
#pragma unroll
            for (int i = 0; i < 8; i++)
#pragma unroll
                for (int j = 0; j < 8; j++) acc[i][j] += av[i]*bv[j];
        }
        __syncthreads();
    }
    float4 bb0 = *(const float4*)&bias[bn + tx*8];
    float4 bb1 = *(const float4*)&bias[bn + tx*8 + 4];
    float bv[8] = {bb0.x, bb0.y, bb0.z, bb0.w, bb1.x, bb1.y, bb1.z, bb1.w};
#pragma unroll
    for (int i = 0; i < 8; i++) {
        size_t row = (size_t)(bm + ty*8 + i);
        float4 o0, o1;
        o0.x = fmaxf(acc[i][0]+bv[0], 0.f); o0.y = fmaxf(acc[i][1]+bv[1], 0.f);
        o0.z = fmaxf(acc[i][2]+bv[2], 0.f); o0.w = fmaxf(acc[i][3]+bv[3], 0.f);
        o1.x = fmaxf(acc[i][4]+bv[4], 0.f); o1.y = fmaxf(acc[i][5]+bv[5], 0.f);
        o1.z = fmaxf(acc[i][6]+bv[6], 0.f); o1.w = fmaxf(acc[i][7]+bv[7], 0.f);
        *(float4*)&Y[row*N + bn + tx*8]     = o0;
        *(float4*)&Y[row*N + bn + tx*8 + 4] = o1;
    }
}

__global__ void maxpool_kernel(const float* __restrict__ Y, float* __restrict__ out,
                               int P, int ns, int C)
{
    int i = blockIdx.x*blockDim.x + threadIdx.x;
    if (i >= P*C) return;
    int p = i / C, c = i % C;
    const float* base = Y + (size_t)p*ns*C + c;
    float m = base[0];
    for (int n = 1; n < ns; n++) m = fmaxf(m, base[(size_t)n*C]);
    out[i] = m;
}

static inline int cdiv(int a, int b) { return (a + b - 1) / b; }

extern "C" void kernel_launch(void* const* d_in, const int* in_sizes, int n_in,
                              void* d_out, int out_size)
{
    (void)in_sizes; (void)n_in; (void)out_size;
    const float* pc  = (const float*)d_in[0];
    const float* w10 = (const float*)d_in[1],  *b10 = (const float*)d_in[2];
    const float* w11 = (const float*)d_in[3],  *b11 = (const float*)d_in[4];
    const float* w12 = (const float*)d_in[5],  *b12 = (const float*)d_in[6];
    const float* w20 = (const float*)d_in[7],  *b20 = (const float*)d_in[8];
    const float* w21 = (const float*)d_in[9],  *b21 = (const float*)d_in[10];
    const float* w22 = (const float*)d_in[11], *b22 = (const float*)d_in[12];
    const float* w30 = (const float*)d_in[13], *b30 = (const float*)d_in[14];
    const float* w31 = (const float*)d_in[15], *b31 = (const float*)d_in[16];
    const float* w32 = (const float*)d_in[17], *b32 = (const float*)d_in[18];
    const float* w40 = (const float*)d_in[19], *b40 = (const float*)d_in[20];
    const float* w41 = (const float*)d_in[21], *b41 = (const float*)d_in[22];
    const float* w42 = (const float*)d_in[23], *b42 = (const float*)d_in[24];

    float *nx1, *nx2, *nx3, *f1, *f2, *f3, *X0, *YA, *YB;
    float4 *pk4;
    int *fidx, *nidx;
    cudaGetSymbolAddress((void**)&nx1,  g_nx1);
    cudaGetSymbolAddress((void**)&nx2,  g_nx2);
    cudaGetSymbolAddress((void**)&nx3,  g_nx3);
    cudaGetSymbolAddress((void**)&f1,   g_f1);
    cudaGetSymbolAddress((void**)&f2,   g_f2);
    cudaGetSymbolAddress((void**)&f3,   g_f3);
    cudaGetSymbolAddress((void**)&X0,   g_X0);
    cudaGetSymbolAddress((void**)&YA,   g_YA);
    cudaGetSymbolAddress((void**)&YB,   g_YB);
    cudaGetSymbolAddress((void**)&fidx, g_fidx);
    cudaGetSymbolAddress((void**)&nidx, g_nidx);
    cudaGetSymbolAddress((void**)&pk4,  g_pk4);

    cudaFuncSetAttribute((const void*)sa1_kernel,
                         cudaFuncAttributeMaxDynamicSharedMemorySize, SA1_SMEM*4);

    float* out = (float*)d_out;
    float* nx4 = out;          // [4,256,3]
    float* f4  = out + 3072;   // [4,256,512]

    // Stage 1: 16384 -> 2048, r=0.2, ns=64
    pack4_kernel<<<cdiv(NB*16384,256),256>>>(pc, pk4, NB*16384);
    fps1_cluster<<<NB*CLU, 1024>>>(pc, fidx);
    gather_xyz<<<cdiv(NB*2048*3,256),256>>>(pc, fidx, nx1, 2048, 16384, NB*2048*3);
    ball_query4<<<cdiv(NB*2048*32,256),256>>>(pk4, nx1, nidx, 2048, 16384, 64, 0.04f, NB*2048);
    sa1_kernel<<<NB*2048, 128, SA1_SMEM*4>>>(pc, nx1, nidx, w10,b10,w11,b11,w12,b12, f1, 0.2f);

    // Stage 2: 2048 -> 1024, r=0.4, ns=32, MLP 131->128->128->256
    fps_reg_kernel<512,4><<<NB, 512, 3*2048*4>>>(nx1, 1024, fidx);
    gather_xyz<<<cdiv(NB*1024*3,256),256>>>(nx1, fidx, nx2, 1024, 2048, NB*1024*3);
    ball_query_kernel<<<cdiv(NB*1024*32,256),256>>>(nx1, nx2, nidx, 1024, 2048, 32, 0.16f, NB*1024);
    group_kernel<<<cdiv(NB*1024*32*131,256),256>>>(nx1, nx2, nidx, f1, X0, 1024, 2048, 32, 128, 0.4f, NB*1024*32*131);
    gemm128<<<dim3(1, 1024), 256>>>(X0, w20, b20, YA, 131072, 128, 131);
    gemm128<<<dim3(1, 1024), 256>>>(YA, w21, b21, YB, 131072, 128, 128);
    gemm128<<<dim3(2, 1024), 256>>>(YB, w22, b22, YA, 131072, 256, 128);
    maxpool_kernel<<<cdiv(NB*1024*256,256),256>>>(YA, f2, NB*1024, 32, 256);

    // Stage 3: 1024 -> 512, r=0.6, ns=16, MLP 259->256->256->512
    fps_reg_kernel<256,4><<<NB, 256, 3*1024*4>>>(nx2, 512, fidx);
    gather_xyz<<<cdiv(NB*512*3,256),256>>>(nx2, fidx, nx3, 512, 1024, NB*512*3);
    ball_query_kernel<<<cdiv(NB*512*32,256),256>>>(nx2, nx3, nidx, 512, 1024, 16, 0.36f, NB*512);
    group_kernel<<<cdiv(NB*512*16*259,256),256>>>(nx2, nx3, nidx, f2, X0, 512, 1024, 16, 256, 0.6f, NB*512*16*259);
    gemm128<<<dim3(2, 256), 256>>>(X0, w30, b30, YA, 32768, 256, 259);
    gemm128<<<dim3(2, 256), 256>>>(YA, w31, b31, YB, 32768, 256, 256);
    gemm128<<<dim3(4, 256), 256>>>(YB, w32, b32, YA, 32768, 512, 256);
    maxpool_kernel<<<cdiv(NB*512*512,256),256>>>(YA, f3, NB*512, 16, 512);

    // Stage 4: 512 -> 256, r=1.2, ns=8, MLP 515->512->512->512
    fps_reg_kernel<128,4><<<NB, 128, 3*512*4>>>(nx3, 256, fidx);
    gather_xyz<<<cdiv(NB*256*3,256),256>>>(nx3, fidx, nx4, 256, 512, NB*256*3);
    ball_query_kernel<<<cdiv(NB*256*32,256),256>>>(nx3, nx4, nidx, 256, 512, 8, 1.44f, NB*256);
    group_kernel<<<cdiv(NB*256*8*515,256),256>>>(nx3, nx4, nidx, f3, X0, 256, 512, 8, 512, 1.2f, NB*256*8*515);
    gemm128<<<dim3(4, 64), 256>>>(X0, w40, b40, YA, 8192, 512, 515);
    gemm128<<<dim3(4, 64), 256>>>(YA, w41, b41, YB, 8192, 512, 512);
    gemm128<<<dim3(4, 64), 256>>>(YB, w42, b42, YA, 8192, 512, 512);
    maxpool_kernel<<<cdiv(NB*256*512,256),256>>>(YA, f4, NB*256, 8, 512);
}